// round 3
// baseline (speedup 1.0000x reference)
#include <cuda_runtime.h>
#include <cuda_bf16.h>
#include <math.h>

// ---------------------------------------------------------------------------
// RGCN layer, restructured:
//   S[d]   = sum_{e: dst[e]=d} (h[src[e]] + emb_rel[etype[e]])      (edge pass)
//   agg    = S @ W_neighbor                                          (GEMM)
//   loop   = h @ W_loop          (deg>0)   |  h @ W_evolve (deg==0, ~0.25%)
//   gate   = sigmoid(prev_h @ W_skip + b)
//   out    = relu(gate * (agg*norm + loop) + (1-gate)*prev_h)
// Moving the shared linear map outside the segment-sum turns 600k per-edge
// GEMVs into one 100k-row GEMM: 60x less FLOP, edge pass is pure memory.
// NOTE: src/dst/etype are int32 on device (JAX default x64-disabled downcasts
// the reference's int64 randint to int32).
// ---------------------------------------------------------------------------

#define NMAX 100000
#define D 128

__device__ float4 g_S4[NMAX * (D / 4)];   // 51.2 MB scratch accumulator
__device__ int    g_flag[NMAX];
__device__ int    g_list[NMAX];
__device__ int    g_cnt;

// ---------------------------------------------------------------------------
// Edge pass: one warp per edge. Lane l handles floats [4l, 4l+4).
// ---------------------------------------------------------------------------
__global__ void edge_kernel(const float* __restrict__ h,
                            const float* __restrict__ emb,
                            const int* __restrict__ src,
                            const int* __restrict__ dst,
                            const int* __restrict__ et,
                            int E) {
    int w = (blockIdx.x * blockDim.x + threadIdx.x) >> 5;
    if (w >= E) return;
    int lane = threadIdx.x & 31;
    int s = __ldg(src + w);
    int d = __ldg(dst + w);
    int r = __ldg(et + w);
    float4 hv = ((const float4*)(h + (size_t)s * D))[lane];
    float4 rv = ((const float4*)(emb + (size_t)r * D))[lane];
    float4 v = make_float4(hv.x + rv.x, hv.y + rv.y, hv.z + rv.z, hv.w + rv.w);
    float* p = (float*)&g_S4[(size_t)d * (D / 4) + lane];
    asm volatile("red.global.add.v4.f32 [%0], {%1,%2,%3,%4};"
                 :: "l"(p), "f"(v.x), "f"(v.y), "f"(v.z), "f"(v.w) : "memory");
    if (lane == 0) g_flag[d] = 1;
}

// ---------------------------------------------------------------------------
// Build list of degree-0 nodes (expected ~250 of 100k).
// ---------------------------------------------------------------------------
__global__ void build_list(int N) {
    int n = blockIdx.x * blockDim.x + threadIdx.x;
    if (n < N && g_flag[n] == 0) {
        int p = atomicAdd(&g_cnt, 1);
        g_list[p] = n;
    }
}

// ---------------------------------------------------------------------------
// Fused node pass: 3 GEMM phases over a 64-node tile, all with W staged in
// SMEM.  blockDim=256: jq = tid&31 owns cols [4jq,4jq+4), ig = tid>>5 owns
// local rows [8ig, 8ig+8).
// ---------------------------------------------------------------------------
__device__ __forceinline__ void load_tiles(const float* __restrict__ Xg,
                                           const float* __restrict__ Wg,
                                           float* sW, float* sX,
                                           int node0, int N, int tid) {
    const float4* Wg4 = (const float4*)Wg;
    float4* sW4 = (float4*)sW;
    #pragma unroll
    for (int i = 0; i < 16; i++)                 // 128x128 floats = 4096 f4
        sW4[tid + i * 256] = Wg4[tid + i * 256];
    float4* sX4 = (float4*)sX;
    #pragma unroll
    for (int i = 0; i < 8; i++) {                // 64x128 floats = 2048 f4
        int idx = tid + i * 256;
        int row = idx >> 5;
        int c4  = idx & 31;
        float4 v = make_float4(0.f, 0.f, 0.f, 0.f);
        if (node0 + row < N)
            v = ((const float4*)(Xg + (size_t)(node0 + row) * D))[c4];
        sX4[idx] = v;
    }
}

__device__ __forceinline__ void gemm_tile(const float* sW, const float* sX,
                                          float4* acc, int ig, int jq) {
    #pragma unroll
    for (int i = 0; i < 8; i++) acc[i] = make_float4(0.f, 0.f, 0.f, 0.f);
    const float4* sW4 = (const float4*)sW;
    #pragma unroll 4
    for (int k = 0; k < D; k++) {
        float4 w = sW4[k * 32 + jq];
        #pragma unroll
        for (int i = 0; i < 8; i++) {
            float x = sX[(ig * 8 + i) * D + k];
            acc[i].x = fmaf(x, w.x, acc[i].x);
            acc[i].y = fmaf(x, w.y, acc[i].y);
            acc[i].z = fmaf(x, w.z, acc[i].z);
            acc[i].w = fmaf(x, w.w, acc[i].w);
        }
    }
}

__global__ __launch_bounds__(256, 1)
void node_kernel(const float* __restrict__ h,
                 const float* __restrict__ prev,
                 const float* __restrict__ norm,
                 const float* __restrict__ Wn,
                 const float* __restrict__ Wl,
                 const float* __restrict__ Wsk,
                 const float* __restrict__ bias,
                 float* __restrict__ out, int N) {
    extern __shared__ float smem[];
    float* sW   = smem;              // 16384 floats (64 KB)
    float* sX   = smem + 16384;      //  8192 floats (32 KB)
    float* sRes = smem + 24576;      //  8192 floats (32 KB)
    float4* sRes4 = (float4*)sRes;
    float4* sX4   = (float4*)sX;

    int tid = threadIdx.x;
    int jq  = tid & 31;
    int ig  = tid >> 5;
    int node0 = blockIdx.x * 64;
    float4 acc[8];

    // ---- Phase A: agg = S @ Wn ; sRes = agg * norm ----
    load_tiles((const float*)g_S4, Wn, sW, sX, node0, N, tid);
    __syncthreads();
    gemm_tile(sW, sX, acc, ig, jq);
    #pragma unroll
    for (int i = 0; i < 8; i++) {
        int row = ig * 8 + i;
        float nv = (node0 + row < N) ? norm[node0 + row] : 0.f;
        float4 a = acc[i];
        a.x *= nv; a.y *= nv; a.z *= nv; a.w *= nv;
        sRes4[row * 32 + jq] = a;
    }
    __syncthreads();

    // ---- Phase B: loop = h @ Wl ; sRes += loop ----
    load_tiles(h, Wl, sW, sX, node0, N, tid);
    __syncthreads();
    gemm_tile(sW, sX, acc, ig, jq);
    #pragma unroll
    for (int i = 0; i < 8; i++) {
        int row = ig * 8 + i;
        float4 r = sRes4[row * 32 + jq];
        r.x += acc[i].x; r.y += acc[i].y; r.z += acc[i].z; r.w += acc[i].w;
        sRes4[row * 32 + jq] = r;
    }
    __syncthreads();

    // ---- Phase C: gate = sigmoid(prev @ Wsk + b); blend + relu ----
    load_tiles(prev, Wsk, sW, sX, node0, N, tid);   // sX now holds prev tile
    __syncthreads();
    gemm_tile(sW, sX, acc, ig, jq);
    float4 b4 = ((const float4*)bias)[jq];
    #pragma unroll
    for (int i = 0; i < 8; i++) {
        int row = ig * 8 + i;
        if (node0 + row >= N) continue;
        float4 sk = acc[i];
        float4 r  = sRes4[row * 32 + jq];
        float4 p  = sX4[row * 32 + jq];
        float4 o;
        float g;
        g   = 1.f / (1.f + expf(-(sk.x + b4.x)));
        o.x = fmaxf(g * r.x + (1.f - g) * p.x, 0.f);
        g   = 1.f / (1.f + expf(-(sk.y + b4.y)));
        o.y = fmaxf(g * r.y + (1.f - g) * p.y, 0.f);
        g   = 1.f / (1.f + expf(-(sk.z + b4.z)));
        o.z = fmaxf(g * r.z + (1.f - g) * p.z, 0.f);
        g   = 1.f / (1.f + expf(-(sk.w + b4.w)));
        o.w = fmaxf(g * r.w + (1.f - g) * p.w, 0.f);
        ((float4*)(out + (size_t)(node0 + row) * D))[jq] = o;
    }
}

// ---------------------------------------------------------------------------
// Fix-up for degree-0 nodes: their agg row is exactly 0, so recompute
//   out = relu(gate * (h @ W_evolve) + (1-gate)*prev)
// One block (128 threads) per listed node, strided.
// ---------------------------------------------------------------------------
__global__ void fix_kernel(const float* __restrict__ h,
                           const float* __restrict__ prev,
                           const float* __restrict__ We,
                           const float* __restrict__ Wsk,
                           const float* __restrict__ bias,
                           float* __restrict__ out) {
    __shared__ float sh[D], sp[D];
    int t = threadIdx.x;
    int cnt = g_cnt;
    for (int ii = blockIdx.x; ii < cnt; ii += gridDim.x) {
        int node = g_list[ii];
        __syncthreads();
        sh[t] = h[(size_t)node * D + t];
        sp[t] = prev[(size_t)node * D + t];
        __syncthreads();
        float lp = 0.f, sk = 0.f;
        #pragma unroll 4
        for (int k = 0; k < D; k++) {
            lp = fmaf(sh[k], We[k * D + t], lp);
            sk = fmaf(sp[k], Wsk[k * D + t], sk);
        }
        float g = 1.f / (1.f + expf(-(sk + bias[t])));
        out[(size_t)node * D + t] = fmaxf(g * lp + (1.f - g) * sp[t], 0.f);
    }
}

// ---------------------------------------------------------------------------
extern "C" void kernel_launch(void* const* d_in, const int* in_sizes, int n_in,
                              void* d_out, int out_size) {
    const float* h    = (const float*)d_in[0];
    const float* prev = (const float*)d_in[1];
    const float* emb  = (const float*)d_in[2];
    const float* norm = (const float*)d_in[3];
    const float* Wn   = (const float*)d_in[4];
    const float* Wl   = (const float*)d_in[5];
    const float* We   = (const float*)d_in[6];
    const float* Wsk  = (const float*)d_in[7];
    const float* bias = (const float*)d_in[8];
    const int* src = (const int*)d_in[9];     // int32: JAX x64-disabled
    const int* dst = (const int*)d_in[10];
    const int* et  = (const int*)d_in[11];
    int N = in_sizes[3];                 // norm has exactly N elements
    if (N > NMAX) N = NMAX;
    int E = in_sizes[9];
    float* out = (float*)d_out;

    void *pS, *pF, *pC;
    cudaGetSymbolAddress(&pS, g_S4);
    cudaGetSymbolAddress(&pF, g_flag);
    cudaGetSymbolAddress(&pC, g_cnt);
    cudaMemsetAsync(pS, 0, (size_t)N * D * sizeof(float), 0);
    cudaMemsetAsync(pF, 0, (size_t)N * sizeof(int), 0);
    cudaMemsetAsync(pC, 0, sizeof(int), 0);

    int edgeBlocks = (E + 7) / 8;                 // 8 warps/block, 1 warp/edge
    edge_kernel<<<edgeBlocks, 256>>>(h, emb, src, dst, et, E);

    build_list<<<(N + 255) / 256, 256>>>(N);

    cudaFuncSetAttribute(node_kernel,
                         cudaFuncAttributeMaxDynamicSharedMemorySize, 131072);
    node_kernel<<<(N + 63) / 64, 256, 131072>>>(h, prev, norm, Wn, Wl, Wsk,
                                                bias, out, N);

    fix_kernel<<<128, 128>>>(h, prev, We, Wsk, bias, out);
}